// round 12
// baseline (speedup 1.0000x reference)
#include <cuda_runtime.h>
#include <cuda_bf16.h>
#include <cstdint>

#define CS   1024
#define HD   16
#define DDIM 64
#define CZ   128
#define NI   1024
#define NJ   1024
#define BK   64

typedef unsigned long long ull;

// ---------------- scratch (device globals: allocation-free) ----------------
__device__ float g_g[NI * CS];                  // 4 MB (gate, fp32)
__device__ float g_z[(size_t)HD * NI * NJ];     // 64 MB

// bf16 hi/lo split matrices (2 MB each)
__device__ __nv_bfloat16 g_s_h[NI * CS],   g_s_l[NI * CS];
__device__ __nv_bfloat16 g_kin_h[NJ * CS], g_kin_l[NJ * CS];
__device__ __nv_bfloat16 g_wq_h[CS * CS],  g_wq_l[CS * CS];
__device__ __nv_bfloat16 g_wk_h[CS * CS],  g_wk_l[CS * CS];
__device__ __nv_bfloat16 g_wv_h[CS * CS],  g_wv_l[CS * CS];
__device__ __nv_bfloat16 g_wg_h[CS * CS],  g_wg_l[CS * CS];
__device__ __nv_bfloat16 g_wo_h[CS * CS],  g_wo_l[CS * CS];
__device__ __nv_bfloat16 g_qh[NI * CS],  g_ql[NI * CS];      // q/8 (bias folded)
__device__ __nv_bfloat16 g_kh[NJ * CS],  g_kl[NJ * CS];
__device__ __nv_bfloat16 g_vh[NJ * CS],  g_vl[NJ * CS];
__device__ __nv_bfloat16 g_go_h[NI * CS], g_go_l[NI * CS];   // g .* o from attn

// ---------------- packed fp32x2 helpers (z kernel) ----------------
static __device__ __forceinline__ ull f2pack(float x, float y) {
    ull r; asm("mov.b64 %0, {%1, %2};" : "=l"(r) : "f"(x), "f"(y)); return r;
}
static __device__ __forceinline__ ull f2dup(float x) {
    ull r; asm("mov.b64 %0, {%1, %1};" : "=l"(r) : "f"(x)); return r;
}
static __device__ __forceinline__ void ffma2(ull& d, ull a, ull b) {
    asm("fma.rn.f32x2 %0, %1, %2, %0;" : "+l"(d) : "l"(a), "l"(b));
}
static __device__ __forceinline__ float2 f2unpack(ull v) {
    float2 r; asm("mov.b64 {%0, %1}, %2;" : "=f"(r.x), "=f"(r.y) : "l"(v)); return r;
}

// ---------------- mma.sync / ldmatrix / cp.async helpers (baseline PTX) -----
static __device__ __forceinline__ uint32_t smem_to_u32(const void* p) {
    uint32_t a;
    asm("{ .reg .u64 t; cvta.to.shared.u64 t, %1; cvt.u32.u64 %0, t; }" : "=r"(a) : "l"(p));
    return a;
}
static __device__ __forceinline__ void ldsm4(uint32_t* r, uint32_t addr) {
    asm volatile("ldmatrix.sync.aligned.m8n8.x4.shared.b16 {%0,%1,%2,%3}, [%4];"
                 : "=r"(r[0]), "=r"(r[1]), "=r"(r[2]), "=r"(r[3]) : "r"(addr));
}
static __device__ __forceinline__ void ldsm4_t(uint32_t* r, uint32_t addr) {
    asm volatile("ldmatrix.sync.aligned.m8n8.x4.trans.shared.b16 {%0,%1,%2,%3}, [%4];"
                 : "=r"(r[0]), "=r"(r[1]), "=r"(r[2]), "=r"(r[3]) : "r"(addr));
}
static __device__ __forceinline__ void mma16816(float* c, const uint32_t* a, const uint32_t* b) {
    asm volatile("mma.sync.aligned.m16n8k16.row.col.f32.bf16.bf16.f32 "
                 "{%0,%1,%2,%3}, {%4,%5,%6,%7}, {%8,%9}, {%0,%1,%2,%3};"
                 : "+f"(c[0]), "+f"(c[1]), "+f"(c[2]), "+f"(c[3])
                 : "r"(a[0]), "r"(a[1]), "r"(a[2]), "r"(a[3]), "r"(b[0]), "r"(b[1]));
}
#define CP_ASYNC16(smem, gptr) \
    asm volatile("cp.async.cg.shared.global [%0], [%1], 16;" \
                 :: "r"(smem), "l"(gptr) : "memory")
#define CP_COMMIT() asm volatile("cp.async.commit_group;" ::: "memory")
#define CP_WAIT1()  asm volatile("cp.async.wait_group 1;" ::: "memory")
#define CP_WAIT0()  asm volatile("cp.async.wait_group 0;" ::: "memory")

static __device__ __forceinline__ void cvt_hilo(float v, __nv_bfloat16& h, __nv_bfloat16& l) {
    h = __float2bfloat16(v);
    l = __float2bfloat16(v - __bfloat162float(h));
}

// =====================================================================
// fp32 -> bf16 hi/lo conversion (s, kin, Wq, Wk, Wv, Wg, Wo)
// =====================================================================
__global__ __launch_bounds__(256) void conv_kernel(
    const float* __restrict__ s, const float* __restrict__ kin,
    const float* __restrict__ Wq, const float* __restrict__ Wk,
    const float* __restrict__ Wv, const float* __restrict__ Wg,
    const float* __restrict__ Wo)
{
    const int which = blockIdx.x >> 6;
    const int slice = blockIdx.x & 63;
    const float* src;
    __nv_bfloat16 *dh, *dl;
    switch (which) {
    case 0: src = s;   dh = g_s_h;   dl = g_s_l;   break;
    case 1: src = kin; dh = g_kin_h; dl = g_kin_l; break;
    case 2: src = Wq;  dh = g_wq_h;  dl = g_wq_l;  break;
    case 3: src = Wk;  dh = g_wk_h;  dl = g_wk_l;  break;
    case 4: src = Wv;  dh = g_wv_h;  dl = g_wv_l;  break;
    case 5: src = Wg;  dh = g_wg_h;  dl = g_wg_l;  break;
    default: src = Wo; dh = g_wo_h;  dl = g_wo_l;  break;
    }
    const int base = slice * 16384;
#pragma unroll 4
    for (int it = 0; it < 16; it++) {
        const int e = base + (it * 256 + threadIdx.x) * 4;
        const float4 v = *(const float4*)&src[e];
        __nv_bfloat16 h0, h1, h2, h3, l0, l1, l2, l3;
        cvt_hilo(v.x, h0, l0); cvt_hilo(v.y, h1, l1);
        cvt_hilo(v.z, h2, l2); cvt_hilo(v.w, h3, l3);
        *(__nv_bfloat162*)&dh[e]     = __halves2bfloat162(h0, h1);
        *(__nv_bfloat162*)&dh[e + 2] = __halves2bfloat162(h2, h3);
        *(__nv_bfloat162*)&dl[e]     = __halves2bfloat162(l0, l1);
        *(__nv_bfloat162*)&dl[e + 2] = __halves2bfloat162(l2, l3);
    }
}

// =====================================================================
// mma.sync bf16x3 GEMM (R10-measured single-stage version, BK=64):
// C[128x128 tile] = A @ B^T.  128B smem rows, swizzle ch ^ (r&7).
// OUT: 0 fp32 plain, 1 (acc+bias)*0.125 -> bf16 hi/lo (q),
//      2 sigmoid -> fp32 (g), 3 plain -> bf16 hi/lo (k, v)
// =====================================================================
#define GEMM_SMEM 65536

template <int OUT>
static __device__ void gemm_mma_body(
    const __nv_bfloat16* __restrict__ Ahg, const __nv_bfloat16* __restrict__ Alg,
    const __nv_bfloat16* __restrict__ Bhg, const __nv_bfloat16* __restrict__ Blg,
    const float* __restrict__ biasv, float* __restrict__ Cf,
    __nv_bfloat16* __restrict__ Ch, __nv_bfloat16* __restrict__ Cl, char* dsm)
{
    const int tid  = threadIdx.x;
    const int warp = tid >> 5, lane = tid & 31;
    const int m0w  = (warp & 3) * 32;
    const int n0w  = (warp >> 2) * 64;
    const int rowA0 = blockIdx.y * 128;
    const int rowB0 = blockIdx.x * 128;
    const uint32_t sbase = smem_to_u32(dsm);
    const uint32_t soff[4] = {0u, 16384u, 32768u, 49152u};

    float acc[2][8][4];
#pragma unroll
    for (int mt = 0; mt < 2; mt++)
#pragma unroll
        for (int nt = 0; nt < 8; nt++)
#pragma unroll
            for (int q = 0; q < 4; q++) acc[mt][nt][q] = 0.f;

    const int a_row = lane & 15;
    const int a_kh  = lane >> 4;
    const int b_row = ((lane >> 4) & 1) * 8 + (lane & 7);
    const int b_kh  = (lane >> 3) & 1;

    for (int c = 0; c < 16; c++) {
        const int kt = c * BK;
        const __nv_bfloat16* gsrc[4] = {Ahg, Alg, Bhg, Blg};
        const int grow[4] = {rowA0, rowA0, rowB0, rowB0};
#pragma unroll
        for (int piece = 0; piece < 4; piece++) {
#pragma unroll
            for (int p = 0; p < 4; p++) {
                const int idx = p * 256 + tid;
                const int r = idx >> 3, ch = idx & 7;
                const uint4 v = *(const uint4*)
                    &gsrc[piece][(size_t)(grow[piece] + r) * CS + kt + ch * 8];
                *(uint4*)(dsm + soff[piece] + r * 128 + ((ch ^ (r & 7)) << 4)) = v;
            }
        }
        __syncthreads();

#pragma unroll
        for (int ks = 0; ks < 4; ks++) {
            uint32_t ah[2][4], al[2][4], bh[8][2], bl[8][2];
#pragma unroll
            for (int mt = 0; mt < 2; mt++) {
                const int r = m0w + mt * 16 + a_row;
                const int ch = ks * 2 + a_kh;
                const uint32_t off = r * 128 + ((ch ^ (r & 7)) << 4);
                ldsm4(ah[mt], sbase + soff[0] + off);
                ldsm4(al[mt], sbase + soff[1] + off);
            }
#pragma unroll
            for (int bq2 = 0; bq2 < 4; bq2++) {
                const int r = n0w + bq2 * 16 + b_row;
                const int ch = ks * 2 + b_kh;
                const uint32_t off = r * 128 + ((ch ^ (r & 7)) << 4);
                uint32_t t[4];
                ldsm4(t, sbase + soff[2] + off);
                bh[2 * bq2][0] = t[0]; bh[2 * bq2][1] = t[1];
                bh[2 * bq2 + 1][0] = t[2]; bh[2 * bq2 + 1][1] = t[3];
                ldsm4(t, sbase + soff[3] + off);
                bl[2 * bq2][0] = t[0]; bl[2 * bq2][1] = t[1];
                bl[2 * bq2 + 1][0] = t[2]; bl[2 * bq2 + 1][1] = t[3];
            }
#pragma unroll
            for (int mt = 0; mt < 2; mt++)
#pragma unroll
                for (int nt = 0; nt < 8; nt++) {
                    mma16816(acc[mt][nt], ah[mt], bh[nt]);
                    mma16816(acc[mt][nt], ah[mt], bl[nt]);
                    mma16816(acc[mt][nt], al[mt], bh[nt]);
                }
        }
        __syncthreads();
    }

    const int g2 = lane >> 2, tig = lane & 3;
#pragma unroll
    for (int mt = 0; mt < 2; mt++)
#pragma unroll
        for (int nt = 0; nt < 8; nt++)
#pragma unroll
            for (int half = 0; half < 2; half++) {
                const int row = rowA0 + m0w + mt * 16 + g2 + half * 8;
                const int col = rowB0 + n0w + nt * 8 + tig * 2;
                float2 v = make_float2(acc[mt][nt][half * 2], acc[mt][nt][half * 2 + 1]);
                if (OUT == 1) {
                    v.x = (v.x + biasv[col]) * 0.125f;
                    v.y = (v.y + biasv[col + 1]) * 0.125f;
                } else if (OUT == 2) {
                    v.x = 1.f / (1.f + __expf(-v.x));
                    v.y = 1.f / (1.f + __expf(-v.y));
                }
                if (OUT == 0 || OUT == 2) {
                    *(float2*)&Cf[(size_t)row * CS + col] = v;
                } else {
                    __nv_bfloat16 h0, h1, l0, l1;
                    cvt_hilo(v.x, h0, l0); cvt_hilo(v.y, h1, l1);
                    *(__nv_bfloat162*)&Ch[(size_t)row * CS + col] = __halves2bfloat162(h0, h1);
                    *(__nv_bfloat162*)&Cl[(size_t)row * CS + col] = __halves2bfloat162(l0, l1);
                }
            }
}

__global__ __launch_bounds__(256) void proj_mma_kernel(const float* __restrict__ bq)
{
    extern __shared__ char dsm[];
    switch (blockIdx.z) {
    case 0: gemm_mma_body<1>(g_s_h,   g_s_l,   g_wq_h, g_wq_l, bq,      nullptr, g_qh, g_ql, dsm); break;
    case 1: gemm_mma_body<3>(g_kin_h, g_kin_l, g_wk_h, g_wk_l, nullptr, nullptr, g_kh, g_kl, dsm); break;
    case 2: gemm_mma_body<3>(g_kin_h, g_kin_l, g_wv_h, g_wv_l, nullptr, nullptr, g_vh, g_vl, dsm); break;
    default: gemm_mma_body<2>(g_s_h,  g_s_l,   g_wg_h, g_wg_l, nullptr, g_g,     nullptr, nullptr, dsm); break;
    }
}

__global__ __launch_bounds__(256) void final_mma_kernel(float* __restrict__ out)
{
    extern __shared__ char dsm[];
    gemm_mma_body<0>(g_go_h, g_go_l, g_wo_h, g_wo_l, nullptr, out, nullptr, nullptr, dsm);
}

// =====================================================================
// z_kernel, cp.async streaming: block = one i-row, 16 tiles of [64 j][128 c]
// double-buffered (2 x 32KB). warp = (h-group hg, j-half jh); lane = one
// j-row, 4 heads. Bias LDS conflict-free (slot = ch ^ (r&31)).
// z[h,i,j] = bias[i,j,:]·Wz[:,h] + (1-mask[j])*(-1e6)
// smem: 65536 (stages) + 8192 (Wzs) = 73728
// =====================================================================
#define Z_SMEM (65536 + 8192)

__global__ __launch_bounds__(256) void z_kernel(
    const float* __restrict__ bias, const float* __restrict__ Wz,
    const float* __restrict__ mask)
{
    extern __shared__ char dsm[];
    const uint32_t sbase = smem_to_u32(dsm);
    ull* Wzs = (ull*)(dsm + 65536);       // Wzs[hp*128 + c] = (Wz[c][2hp], Wz[c][2hp+1])
    const int tid = threadIdx.x;
    for (int t = tid; t < (HD / 2) * CZ; t += 256) {
        const int hp = t >> 7, c = t & 127;
        Wzs[t] = f2pack(Wz[c * HD + hp * 2], Wz[c * HD + hp * 2 + 1]);
    }

    const int i = blockIdx.x;
    const int warp = tid >> 5, lane = tid & 31;
    const int hg = warp & 3;              // heads 4hg..4hg+3
    const int jh = warp >> 2;             // j-half
    const int rl = jh * 32 + lane;        // local j-row 0..63
    const int rx = rl & 31;

    auto load_tile = [&](int jt, int stage) {
#pragma unroll
        for (int p = 0; p < 8; p++) {
            const int idx = p * 256 + tid;
            const int r = idx >> 5, ch = idx & 31;
            const uint32_t dst = sbase + stage * 32768 + r * 512 + ((ch ^ (r & 31)) << 4);
            CP_ASYNC16(dst, bias + ((size_t)i * NJ + jt * 64 + r) * CZ + ch * 4);
        }
        CP_COMMIT();
    };

    load_tile(0, 0);
    for (int t = 0; t < 16; t++) {
        const int stage = t & 1;
        if (t + 1 < 16) { load_tile(t + 1, stage ^ 1); CP_WAIT1(); }
        else            { CP_WAIT0(); }
        __syncthreads();   // tile ready (and Wzs on t=0)

        ull accA = 0ull, accB = 0ull;     // h-pairs 2hg, 2hg+1
        const char* rowp = dsm + stage * 32768 + rl * 512;
#pragma unroll
        for (int c4 = 0; c4 < CZ; c4 += 4) {
            const int ch = c4 >> 2;
            const float4 bv = *(const float4*)(rowp + ((ch ^ rx) << 4));
            const ulonglong2 wA01 = *(const ulonglong2*)&Wzs[(2 * hg) * CZ + c4];
            const ulonglong2 wA23 = *(const ulonglong2*)&Wzs[(2 * hg) * CZ + c4 + 2];
            const ulonglong2 wB01 = *(const ulonglong2*)&Wzs[(2 * hg + 1) * CZ + c4];
            const ulonglong2 wB23 = *(const ulonglong2*)&Wzs[(2 * hg + 1) * CZ + c4 + 2];
            const ull dx = f2dup(bv.x), dy = f2dup(bv.y);
            const ull dz = f2dup(bv.z), dw = f2dup(bv.w);
            ffma2(accA, dx, wA01.x); ffma2(accA, dy, wA01.y);
            ffma2(accA, dz, wA23.x); ffma2(accA, dw, wA23.y);
            ffma2(accB, dx, wB01.x); ffma2(accB, dy, wB01.y);
            ffma2(accB, dz, wB23.x); ffma2(accB, dw, wB23.y);
        }
        const int j = t * 64 + rl;
        const float mterm = (1.0f - mask[j]) * (-1000000.0f);
        const float2 zA = f2unpack(accA), zB = f2unpack(accB);
        const size_t bij = (size_t)i * NJ + j;
        g_z[(size_t)(4 * hg + 0) * NI * NJ + bij] = zA.x + mterm;
        g_z[(size_t)(4 * hg + 1) * NI * NJ + bij] = zA.y + mterm;
        g_z[(size_t)(4 * hg + 2) * NI * NJ + bij] = zB.x + mterm;
        g_z[(size_t)(4 * hg + 3) * NI * NJ + bij] = zB.y + mterm;
        __syncthreads();   // done reading stage before it is overwritten
    }
}

// =====================================================================
// Attention via mma.sync (R10-measured, unchanged)
// =====================================================================
#define ATTN_SMEM 66048

__global__ __launch_bounds__(256) void attn_kernel()
{
    extern __shared__ char dsm[];
    const uint32_t sb = smem_to_u32(dsm);
    const int tid  = threadIdx.x;
    const int warp = tid >> 5, lane = tid & 31;
    const int mt   = warp >> 1;
    const int nh   = warp & 1;
    const int g2   = lane >> 2, tig = lane & 3;
    const int h  = blockIdx.y;
    const int i0 = blockIdx.x * 64;

    const uint32_t Qh = 0, Ql = 8192, Kh = 16384, Kl = 24576,
                   Vh = 32768, Vl = 40960, Ph = 49152, Pl = 57344, LR = 65536;

    const int a_row = lane & 15;
    const int a_kh  = lane >> 4;
    const int b_row = ((lane >> 4) & 1) * 8 + (lane & 7);
    const int b_kh  = (lane >> 3) & 1;
    const int t_row = lane & 15;
    const int t_n8  = (lane >> 4) * 8;

    {
        const __nv_bfloat16* srcs[2] = {g_qh, g_ql};
        const uint32_t dsts[2] = {Qh, Ql};
#pragma unroll
        for (int piece = 0; piece < 2; piece++)
#pragma unroll
            for (int p = 0; p < 2; p++) {
                const int idx = p * 256 + tid;
                const int r = idx >> 3, ch = idx & 7;
                const uint4 v = *(const uint4*)&srcs[piece][(size_t)(i0 + r) * CS + h * DDIM + ch * 8];
                *(uint4*)(dsm + dsts[piece] + r * 128 + ((ch ^ (r & 7)) << 4)) = v;
            }
    }

    float acc_o[4][4];
    float l[2] = {0.f, 0.f};
#pragma unroll
    for (int nt = 0; nt < 4; nt++)
#pragma unroll
        for (int q = 0; q < 4; q++) acc_o[nt][q] = 0.f;

    for (int j0 = 0; j0 < NJ; j0 += 64) {
        __syncthreads();
        {
            const __nv_bfloat16* srcs[4] = {g_kh, g_kl, g_vh, g_vl};
            const uint32_t dsts[4] = {Kh, Kl, Vh, Vl};
#pragma unroll
            for (int piece = 0; piece < 4; piece++)
#pragma unroll
                for (int p = 0; p < 2; p++) {
                    const int idx = p * 256 + tid;
                    const int r = idx >> 3, ch = idx & 7;
                    const uint4 v = *(const uint4*)&srcs[piece][(size_t)(j0 + r) * CS + h * DDIM + ch * 8];
                    *(uint4*)(dsm + dsts[piece] + r * 128 + ((ch ^ (r & 7)) << 4)) = v;
                }
        }
        __syncthreads();

        float acc_s[4][4];
#pragma unroll
        for (int nt = 0; nt < 4; nt++)
#pragma unroll
            for (int q = 0; q < 4; q++) acc_s[nt][q] = 0.f;

#pragma unroll
        for (int ks = 0; ks < 4; ks++) {
            uint32_t ah[4], al[4];
            {
                const int r = mt * 16 + a_row;
                const int ch = ks * 2 + a_kh;
                const uint32_t off = r * 128 + ((ch ^ (r & 7)) << 4);
                ldsm4(ah, sb + Qh + off);
                ldsm4(al, sb + Ql + off);
            }
            uint32_t bh[4][2], bl[4][2];
#pragma unroll
            for (int bq2 = 0; bq2 < 2; bq2++) {
                const int r = nh * 32 + bq2 * 16 + b_row;
                const int ch = ks * 2 + b_kh;
                const uint32_t off = r * 128 + ((ch ^ (r & 7)) << 4);
                uint32_t t[4];
                ldsm4(t, sb + Kh + off);
                bh[2 * bq2][0] = t[0]; bh[2 * bq2][1] = t[1];
                bh[2 * bq2 + 1][0] = t[2]; bh[2 * bq2 + 1][1] = t[3];
                ldsm4(t, sb + Kl + off);
                bl[2 * bq2][0] = t[0]; bl[2 * bq2][1] = t[1];
                bl[2 * bq2 + 1][0] = t[2]; bl[2 * bq2 + 1][1] = t[3];
            }
#pragma unroll
            for (int nt = 0; nt < 4; nt++) {
                mma16816(acc_s[nt], ah, bh[nt]);
                mma16816(acc_s[nt], ah, bl[nt]);
                mma16816(acc_s[nt], al, bh[nt]);
            }
        }

#pragma unroll
        for (int nt = 0; nt < 4; nt++)
#pragma unroll
            for (int half = 0; half < 2; half++) {
                const int rl = mt * 16 + g2 + half * 8;
                const int cl = nh * 32 + nt * 8 + tig * 2;
                const float2 zv = *(const float2*)
                    &g_z[((size_t)h * NI + (i0 + rl)) * NJ + j0 + cl];
                const float p0 = __expf(acc_s[nt][half * 2]     + zv.x);
                const float p1 = __expf(acc_s[nt][half * 2 + 1] + zv.y);
                l[half] += p0 + p1;
                __nv_bfloat16 h0, h1, l0, l1;
                cvt_hilo(p0, h0, l0); cvt_hilo(p1, h1, l1);
                const uint32_t byte = cl * 2;
                const uint32_t off = rl * 128 + ((((byte >> 4) ^ (rl & 7))) << 4) + (byte & 15);
                *(__nv_bfloat162*)(dsm + Ph + off) = __halves2bfloat162(h0, h1);
                *(__nv_bfloat162*)(dsm + Pl + off) = __halves2bfloat162(l0, l1);
            }
        __syncthreads();

#pragma unroll
        for (int ks = 0; ks < 4; ks++) {
            uint32_t ph_[4], pl_[4];
            {
                const int r = mt * 16 + a_row;
                const int ch = ks * 2 + a_kh;
                const uint32_t off = r * 128 + ((ch ^ (r & 7)) << 4);
                ldsm4(ph_, sb + Ph + off);
                ldsm4(pl_, sb + Pl + off);
            }
            uint32_t vh_[4][2], vl_[4][2];
#pragma unroll
            for (int bq2 = 0; bq2 < 2; bq2++) {
                const int r = ks * 16 + t_row;
                const int n0 = nh * 32 + bq2 * 16 + t_n8;
                const int ch = n0 >> 3;
                const uint32_t off = r * 128 + ((ch ^ (r & 7)) << 4);
                uint32_t t[4];
                ldsm4_t(t, sb + Vh + off);
                vh_[2 * bq2][0] = t[0]; vh_[2 * bq2][1] = t[1];
                vh_[2 * bq2 + 1][0] = t[2]; vh_[2 * bq2 + 1][1] = t[3];
                ldsm4_t(t, sb + Vl + off);
                vl_[2 * bq2][0] = t[0]; vl_[2 * bq2][1] = t[1];
                vl_[2 * bq2 + 1][0] = t[2]; vl_[2 * bq2 + 1][1] = t[3];
            }
#pragma unroll
            for (int nt = 0; nt < 4; nt++) {
                mma16816(acc_o[nt], ph_, vh_[nt]);
                mma16816(acc_o[nt], pl_, vh_[nt]);
                mma16816(acc_o[nt], ph_, vl_[nt]);
            }
        }
    }

#pragma unroll
    for (int half = 0; half < 2; half++) {
        l[half] += __shfl_xor_sync(0xffffffffu, l[half], 1);
        l[half] += __shfl_xor_sync(0xffffffffu, l[half], 2);
    }
    if (tig == 0) {
        ((float*)(dsm + LR))[(mt * 16 + g2) * 2 + nh]     = l[0];
        ((float*)(dsm + LR))[(mt * 16 + g2 + 8) * 2 + nh] = l[1];
    }
    __syncthreads();

#pragma unroll
    for (int half = 0; half < 2; half++) {
        const int rl = mt * 16 + g2 + half * 8;
        const float lt = ((float*)(dsm + LR))[rl * 2] + ((float*)(dsm + LR))[rl * 2 + 1];
        const float inv = 1.f / lt;
        const int row = i0 + rl;
#pragma unroll
        for (int nt = 0; nt < 4; nt++) {
            const int dcol = h * DDIM + nh * 32 + nt * 8 + tig * 2;
            const size_t pos = (size_t)row * CS + dcol;
            const float2 gv = *(const float2*)&g_g[pos];
            const float o0 = acc_o[nt][half * 2]     * inv * gv.x;
            const float o1 = acc_o[nt][half * 2 + 1] * inv * gv.y;
            __nv_bfloat16 h0, h1, l0, l1;
            cvt_hilo(o0, h0, l0); cvt_hilo(o1, h1, l1);
            *(__nv_bfloat162*)&g_go_h[pos] = __halves2bfloat162(h0, h1);
            *(__nv_bfloat162*)&g_go_l[pos] = __halves2bfloat162(l0, l1);
        }
    }
}

// =====================================================================
extern "C" void kernel_launch(void* const* d_in, const int* in_sizes, int n_in,
                              void* d_out, int out_size)
{
    (void)in_sizes; (void)n_in; (void)out_size;
    const float* s    = (const float*)d_in[0];
    const float* kin  = (const float*)d_in[1];
    const float* mask = (const float*)d_in[2];
    const float* bias = (const float*)d_in[3];
    const float* Wq   = (const float*)d_in[4];
    const float* bq   = (const float*)d_in[5];
    const float* Wk   = (const float*)d_in[6];
    const float* Wv   = (const float*)d_in[7];
    const float* Wg   = (const float*)d_in[8];
    const float* Wo   = (const float*)d_in[9];
    const float* Wz   = (const float*)d_in[10];
    float* out = (float*)d_out;

    // host-side attribute sets (idempotent, not stream ops)
    cudaFuncSetAttribute(proj_mma_kernel,
                         cudaFuncAttributeMaxDynamicSharedMemorySize, GEMM_SMEM);
    cudaFuncSetAttribute(final_mma_kernel,
                         cudaFuncAttributeMaxDynamicSharedMemorySize, GEMM_SMEM);
    cudaFuncSetAttribute(attn_kernel,
                         cudaFuncAttributeMaxDynamicSharedMemorySize, ATTN_SMEM);
    cudaFuncSetAttribute(z_kernel,
                         cudaFuncAttributeMaxDynamicSharedMemorySize, Z_SMEM);

    conv_kernel<<<7 * 64, 256>>>(s, kin, Wq, Wk, Wv, Wg, Wo);
    proj_mma_kernel<<<dim3(8, 8, 4), 256, GEMM_SMEM>>>(bq);
    z_kernel<<<NI, 256, Z_SMEM>>>(bias, Wz, mask);
    attn_kernel<<<dim3(NI / 64, HD), 256, ATTN_SMEM>>>();
    final_mma_kernel<<<dim3(8, 8), 256, GEMM_SMEM>>>(out);
}

// round 13
// speedup vs baseline: 1.0984x; 1.0984x over previous
#include <cuda_runtime.h>
#include <cuda_bf16.h>
#include <cstdint>

#define CS   1024
#define HD   16
#define DDIM 64
#define CZ   128
#define NI   1024
#define NJ   1024

typedef unsigned long long ull;

// ---------------- scratch (device globals: allocation-free) ----------------
__device__ float g_g[NI * CS];                  // 4 MB (gate, fp32)
__device__ float g_z[(size_t)HD * NI * NJ];     // 64 MB

// bf16 hi/lo split matrices (2 MB each)
__device__ __nv_bfloat16 g_s_h[NI * CS],   g_s_l[NI * CS];
__device__ __nv_bfloat16 g_kin_h[NJ * CS], g_kin_l[NJ * CS];
__device__ __nv_bfloat16 g_wq_h[CS * CS],  g_wq_l[CS * CS];
__device__ __nv_bfloat16 g_wk_h[CS * CS],  g_wk_l[CS * CS];
__device__ __nv_bfloat16 g_wv_h[CS * CS],  g_wv_l[CS * CS];
__device__ __nv_bfloat16 g_wg_h[CS * CS],  g_wg_l[CS * CS];
__device__ __nv_bfloat16 g_wo_h[CS * CS],  g_wo_l[CS * CS];
__device__ __nv_bfloat16 g_qh[NI * CS],  g_ql[NI * CS];      // q/8 (bias folded)
__device__ __nv_bfloat16 g_kh[NJ * CS],  g_kl[NJ * CS];
__device__ __nv_bfloat16 g_vh[NJ * CS],  g_vl[NJ * CS];
__device__ __nv_bfloat16 g_go_h[NI * CS], g_go_l[NI * CS];   // g .* o from attn

// ---------------- packed fp32x2 helpers (z kernel) ----------------
static __device__ __forceinline__ ull f2pack(float x, float y) {
    ull r; asm("mov.b64 %0, {%1, %2};" : "=l"(r) : "f"(x), "f"(y)); return r;
}
static __device__ __forceinline__ ull f2dup(float x) {
    ull r; asm("mov.b64 %0, {%1, %1};" : "=l"(r) : "f"(x)); return r;
}
static __device__ __forceinline__ void ffma2(ull& d, ull a, ull b) {
    asm("fma.rn.f32x2 %0, %1, %2, %0;" : "+l"(d) : "l"(a), "l"(b));
}
static __device__ __forceinline__ float2 f2unpack(ull v) {
    float2 r; asm("mov.b64 {%0, %1}, %2;" : "=f"(r.x), "=f"(r.y) : "l"(v)); return r;
}

// ---------------- mma.sync / ldmatrix / cp.async helpers (baseline PTX) -----
static __device__ __forceinline__ uint32_t smem_to_u32(const void* p) {
    uint32_t a;
    asm("{ .reg .u64 t; cvta.to.shared.u64 t, %1; cvt.u32.u64 %0, t; }" : "=r"(a) : "l"(p));
    return a;
}
static __device__ __forceinline__ void ldsm4(uint32_t* r, uint32_t addr) {
    asm volatile("ldmatrix.sync.aligned.m8n8.x4.shared.b16 {%0,%1,%2,%3}, [%4];"
                 : "=r"(r[0]), "=r"(r[1]), "=r"(r[2]), "=r"(r[3]) : "r"(addr));
}
static __device__ __forceinline__ void ldsm4_t(uint32_t* r, uint32_t addr) {
    asm volatile("ldmatrix.sync.aligned.m8n8.x4.trans.shared.b16 {%0,%1,%2,%3}, [%4];"
                 : "=r"(r[0]), "=r"(r[1]), "=r"(r[2]), "=r"(r[3]) : "r"(addr));
}
static __device__ __forceinline__ void mma16816(float* c, const uint32_t* a, const uint32_t* b) {
    asm volatile("mma.sync.aligned.m16n8k16.row.col.f32.bf16.bf16.f32 "
                 "{%0,%1,%2,%3}, {%4,%5,%6,%7}, {%8,%9}, {%0,%1,%2,%3};"
                 : "+f"(c[0]), "+f"(c[1]), "+f"(c[2]), "+f"(c[3])
                 : "r"(a[0]), "r"(a[1]), "r"(a[2]), "r"(a[3]), "r"(b[0]), "r"(b[1]));
}
#define CP_ASYNC16(smem, gptr) \
    asm volatile("cp.async.cg.shared.global [%0], [%1], 16;" \
                 :: "r"(smem), "l"(gptr) : "memory")
#define CP_COMMIT() asm volatile("cp.async.commit_group;" ::: "memory")
#define CP_WAIT1()  asm volatile("cp.async.wait_group 1;" ::: "memory")
#define CP_WAIT0()  asm volatile("cp.async.wait_group 0;" ::: "memory")

static __device__ __forceinline__ void cvt_hilo(float v, __nv_bfloat16& h, __nv_bfloat16& l) {
    h = __float2bfloat16(v);
    l = __float2bfloat16(v - __bfloat162float(h));
}

// =====================================================================
// fp32 -> bf16 hi/lo conversion (s, kin, Wq, Wk, Wv, Wg, Wo)
// =====================================================================
__global__ __launch_bounds__(256) void conv_kernel(
    const float* __restrict__ s, const float* __restrict__ kin,
    const float* __restrict__ Wq, const float* __restrict__ Wk,
    const float* __restrict__ Wv, const float* __restrict__ Wg,
    const float* __restrict__ Wo)
{
    const int which = blockIdx.x >> 6;
    const int slice = blockIdx.x & 63;
    const float* src;
    __nv_bfloat16 *dh, *dl;
    switch (which) {
    case 0: src = s;   dh = g_s_h;   dl = g_s_l;   break;
    case 1: src = kin; dh = g_kin_h; dl = g_kin_l; break;
    case 2: src = Wq;  dh = g_wq_h;  dl = g_wq_l;  break;
    case 3: src = Wk;  dh = g_wk_h;  dl = g_wk_l;  break;
    case 4: src = Wv;  dh = g_wv_h;  dl = g_wv_l;  break;
    case 5: src = Wg;  dh = g_wg_h;  dl = g_wg_l;  break;
    default: src = Wo; dh = g_wo_h;  dl = g_wo_l;  break;
    }
    const int base = slice * 16384;
#pragma unroll 4
    for (int it = 0; it < 16; it++) {
        const int e = base + (it * 256 + threadIdx.x) * 4;
        const float4 v = *(const float4*)&src[e];
        __nv_bfloat16 h0, h1, h2, h3, l0, l1, l2, l3;
        cvt_hilo(v.x, h0, l0); cvt_hilo(v.y, h1, l1);
        cvt_hilo(v.z, h2, l2); cvt_hilo(v.w, h3, l3);
        *(__nv_bfloat162*)&dh[e]     = __halves2bfloat162(h0, h1);
        *(__nv_bfloat162*)&dh[e + 2] = __halves2bfloat162(h2, h3);
        *(__nv_bfloat162*)&dl[e]     = __halves2bfloat162(l0, l1);
        *(__nv_bfloat162*)&dl[e + 2] = __halves2bfloat162(l2, l3);
    }
}

// =====================================================================
// mma.sync bf16x3 GEMM, cp.async double-buffered BK=32 pipeline
// (R11-measured, -13us vs single-stage). C[128x128 tile] = A @ B^T.
// 64B smem rows, swizzle ch ^ ((r>>1)&3).
// OUT: 0 fp32 plain, 1 (acc+bias)*0.125 -> bf16 hi/lo (q),
//      2 sigmoid -> fp32 (g), 3 plain -> bf16 hi/lo (k, v)
// smem: 2 stages x 4 pieces x 8KB = 64KB
// =====================================================================
#define GEMM_SMEM 65536

template <int OUT>
static __device__ void gemm_mma_body(
    const __nv_bfloat16* __restrict__ Ahg, const __nv_bfloat16* __restrict__ Alg,
    const __nv_bfloat16* __restrict__ Bhg, const __nv_bfloat16* __restrict__ Blg,
    const float* __restrict__ biasv, float* __restrict__ Cf,
    __nv_bfloat16* __restrict__ Ch, __nv_bfloat16* __restrict__ Cl, char* dsm)
{
    const int tid  = threadIdx.x;
    const int warp = tid >> 5, lane = tid & 31;
    const int m0w  = (warp & 3) * 32;
    const int n0w  = (warp >> 2) * 64;
    const int rowA0 = blockIdx.y * 128;
    const int rowB0 = blockIdx.x * 128;
    const uint32_t sbase = smem_to_u32(dsm);

    float acc[2][8][4];
#pragma unroll
    for (int mt = 0; mt < 2; mt++)
#pragma unroll
        for (int nt = 0; nt < 8; nt++)
#pragma unroll
            for (int q = 0; q < 4; q++) acc[mt][nt][q] = 0.f;

    const int a_row = lane & 15;
    const int a_kh  = lane >> 4;
    const int b_row = ((lane >> 4) & 1) * 8 + (lane & 7);
    const int b_kh  = (lane >> 3) & 1;

    const __nv_bfloat16* gsrc[4] = {Ahg, Alg, Bhg, Blg};
    const int grow[4] = {rowA0, rowA0, rowB0, rowB0};

    auto load_chunk = [&](int c, int stage) {
#pragma unroll
        for (int p = 0; p < 8; p++) {
            const int idx = p * 256 + tid;
            const int piece = p >> 1;              // compile-time per unrolled p
            const int rem = idx & 511;
            const int r = rem >> 2, ch = rem & 3;
            const uint32_t dst = sbase + stage * 32768 + piece * 8192
                               + r * 64 + ((ch ^ ((r >> 1) & 3)) << 4);
            CP_ASYNC16(dst, &gsrc[piece][(size_t)(grow[piece] + r) * CS + c * 32 + ch * 8]);
        }
        CP_COMMIT();
    };

    load_chunk(0, 0);
    for (int c = 0; c < 32; c++) {
        const int stage = c & 1;
        if (c + 1 < 32) { load_chunk(c + 1, stage ^ 1); CP_WAIT1(); }
        else            { CP_WAIT0(); }
        __syncthreads();
        const uint32_t sb0 = sbase + stage * 32768;
#pragma unroll
        for (int ks = 0; ks < 2; ks++) {
            uint32_t ah[2][4], al[2][4], bh[8][2], bl[8][2];
#pragma unroll
            for (int mt = 0; mt < 2; mt++) {
                const int r = m0w + mt * 16 + a_row;
                const int ch = ks * 2 + a_kh;
                const uint32_t off = r * 64 + ((ch ^ ((r >> 1) & 3)) << 4);
                ldsm4(ah[mt], sb0 + off);
                ldsm4(al[mt], sb0 + 8192 + off);
            }
#pragma unroll
            for (int bq2 = 0; bq2 < 4; bq2++) {
                const int r = n0w + bq2 * 16 + b_row;
                const int ch = ks * 2 + b_kh;
                const uint32_t off = r * 64 + ((ch ^ ((r >> 1) & 3)) << 4);
                uint32_t t[4];
                ldsm4(t, sb0 + 16384 + off);
                bh[2 * bq2][0] = t[0]; bh[2 * bq2][1] = t[1];
                bh[2 * bq2 + 1][0] = t[2]; bh[2 * bq2 + 1][1] = t[3];
                ldsm4(t, sb0 + 24576 + off);
                bl[2 * bq2][0] = t[0]; bl[2 * bq2][1] = t[1];
                bl[2 * bq2 + 1][0] = t[2]; bl[2 * bq2 + 1][1] = t[3];
            }
#pragma unroll
            for (int mt = 0; mt < 2; mt++)
#pragma unroll
                for (int nt = 0; nt < 8; nt++) {
                    mma16816(acc[mt][nt], ah[mt], bh[nt]);
                    mma16816(acc[mt][nt], ah[mt], bl[nt]);
                    mma16816(acc[mt][nt], al[mt], bh[nt]);
                }
        }
        __syncthreads();
    }

    const int g2 = lane >> 2, tig = lane & 3;
#pragma unroll
    for (int mt = 0; mt < 2; mt++)
#pragma unroll
        for (int nt = 0; nt < 8; nt++)
#pragma unroll
            for (int half = 0; half < 2; half++) {
                const int row = rowA0 + m0w + mt * 16 + g2 + half * 8;
                const int col = rowB0 + n0w + nt * 8 + tig * 2;
                float2 v = make_float2(acc[mt][nt][half * 2], acc[mt][nt][half * 2 + 1]);
                if (OUT == 1) {
                    v.x = (v.x + biasv[col]) * 0.125f;
                    v.y = (v.y + biasv[col + 1]) * 0.125f;
                } else if (OUT == 2) {
                    v.x = 1.f / (1.f + __expf(-v.x));
                    v.y = 1.f / (1.f + __expf(-v.y));
                }
                if (OUT == 0 || OUT == 2) {
                    *(float2*)&Cf[(size_t)row * CS + col] = v;
                } else {
                    __nv_bfloat16 h0, h1, l0, l1;
                    cvt_hilo(v.x, h0, l0); cvt_hilo(v.y, h1, l1);
                    *(__nv_bfloat162*)&Ch[(size_t)row * CS + col] = __halves2bfloat162(h0, h1);
                    *(__nv_bfloat162*)&Cl[(size_t)row * CS + col] = __halves2bfloat162(l0, l1);
                }
            }
}

__global__ __launch_bounds__(256) void proj_mma_kernel(const float* __restrict__ bq)
{
    extern __shared__ char dsm[];
    switch (blockIdx.z) {
    case 0: gemm_mma_body<1>(g_s_h,   g_s_l,   g_wq_h, g_wq_l, bq,      nullptr, g_qh, g_ql, dsm); break;
    case 1: gemm_mma_body<3>(g_kin_h, g_kin_l, g_wk_h, g_wk_l, nullptr, nullptr, g_kh, g_kl, dsm); break;
    case 2: gemm_mma_body<3>(g_kin_h, g_kin_l, g_wv_h, g_wv_l, nullptr, nullptr, g_vh, g_vl, dsm); break;
    default: gemm_mma_body<2>(g_s_h,  g_s_l,   g_wg_h, g_wg_l, nullptr, g_g,     nullptr, nullptr, dsm); break;
    }
}

__global__ __launch_bounds__(256) void final_mma_kernel(float* __restrict__ out)
{
    extern __shared__ char dsm[];
    gemm_mma_body<0>(g_go_h, g_go_l, g_wo_h, g_wo_l, nullptr, out, nullptr, nullptr, dsm);
}

// =====================================================================
// z_kernel (R10-measured version): standalone, JT=2 + register prefetch.
// z[h,i,j] = bias[i,j,:]·Wz[:,h] + (1-mask[j])*(-1e6)
// =====================================================================
__global__ __launch_bounds__(256) void z_kernel(
    const float* __restrict__ bias, const float* __restrict__ Wz,
    const float* __restrict__ mask)
{
    __shared__ ull Wzs[(HD / 2) * CZ];   // Wzs[hp*128+c] = (Wz[c][2hp], Wz[c][2hp+1])
    for (int t = threadIdx.x; t < (HD / 2) * CZ; t += 256) {
        const int hp = t >> 7, c = t & 127;
        Wzs[t] = f2pack(Wz[c * HD + hp * 2], Wz[c * HD + hp * 2 + 1]);
    }
    __syncthreads();

    const int idx = blockIdx.x;                     // 0..2047
    const int i   = idx >> 1;
    const int jb  = (idx & 1) * 512 + threadIdx.x;  // j = jb + t*256, t in {0,1}
    const float* base = bias + (size_t)i * NJ * CZ;

    ull acc2[2][HD / 2];
#pragma unroll
    for (int t = 0; t < 2; t++)
#pragma unroll
        for (int hp = 0; hp < HD / 2; hp++) acc2[t][hp] = 0ull;

    float4 bv[2];
#pragma unroll
    for (int t = 0; t < 2; t++)
        bv[t] = *(const float4*)&base[(size_t)(jb + t * 256) * CZ];

    for (int c4 = 0; c4 < CZ; c4 += 4) {
        float4 nv[2];
        if (c4 + 4 < CZ) {
#pragma unroll
            for (int t = 0; t < 2; t++)
                nv[t] = *(const float4*)&base[(size_t)(jb + t * 256) * CZ + c4 + 4];
        }
        {
            ull d0[2], d1[2];
#pragma unroll
            for (int t = 0; t < 2; t++) { d0[t] = f2dup(bv[t].x); d1[t] = f2dup(bv[t].y); }
#pragma unroll
            for (int hp = 0; hp < HD / 2; hp++) {
                const ulonglong2 w = *(const ulonglong2*)&Wzs[hp * CZ + c4];
#pragma unroll
                for (int t = 0; t < 2; t++) {
                    ffma2(acc2[t][hp], d0[t], w.x);
                    ffma2(acc2[t][hp], d1[t], w.y);
                }
            }
        }
        {
            ull d0[2], d1[2];
#pragma unroll
            for (int t = 0; t < 2; t++) { d0[t] = f2dup(bv[t].z); d1[t] = f2dup(bv[t].w); }
#pragma unroll
            for (int hp = 0; hp < HD / 2; hp++) {
                const ulonglong2 w = *(const ulonglong2*)&Wzs[hp * CZ + c4 + 2];
#pragma unroll
                for (int t = 0; t < 2; t++) {
                    ffma2(acc2[t][hp], d0[t], w.x);
                    ffma2(acc2[t][hp], d1[t], w.y);
                }
            }
        }
#pragma unroll
        for (int t = 0; t < 2; t++) bv[t] = nv[t];
    }

#pragma unroll
    for (int t = 0; t < 2; t++) {
        const int j = jb + t * 256;
        const float mterm = (1.0f - mask[j]) * (-1000000.0f);
#pragma unroll
        for (int hp = 0; hp < HD / 2; hp++) {
            const float2 zz = f2unpack(acc2[t][hp]);
            g_z[((size_t)(2 * hp + 0) * NI + i) * NJ + j] = zz.x + mterm;
            g_z[((size_t)(2 * hp + 1) * NI + i) * NJ + j] = zz.y + mterm;
        }
    }
}

// =====================================================================
// Attention via mma.sync (R10-measured, unchanged)
// =====================================================================
#define ATTN_SMEM 66048

__global__ __launch_bounds__(256) void attn_kernel()
{
    extern __shared__ char dsm[];
    const uint32_t sb = smem_to_u32(dsm);
    const int tid  = threadIdx.x;
    const int warp = tid >> 5, lane = tid & 31;
    const int mt   = warp >> 1;
    const int nh   = warp & 1;
    const int g2   = lane >> 2, tig = lane & 3;
    const int h  = blockIdx.y;
    const int i0 = blockIdx.x * 64;

    const uint32_t Qh = 0, Ql = 8192, Kh = 16384, Kl = 24576,
                   Vh = 32768, Vl = 40960, Ph = 49152, Pl = 57344, LR = 65536;

    const int a_row = lane & 15;
    const int a_kh  = lane >> 4;
    const int b_row = ((lane >> 4) & 1) * 8 + (lane & 7);
    const int b_kh  = (lane >> 3) & 1;
    const int t_row = lane & 15;
    const int t_n8  = (lane >> 4) * 8;

    {
        const __nv_bfloat16* srcs[2] = {g_qh, g_ql};
        const uint32_t dsts[2] = {Qh, Ql};
#pragma unroll
        for (int piece = 0; piece < 2; piece++)
#pragma unroll
            for (int p = 0; p < 2; p++) {
                const int idx = p * 256 + tid;
                const int r = idx >> 3, ch = idx & 7;
                const uint4 v = *(const uint4*)&srcs[piece][(size_t)(i0 + r) * CS + h * DDIM + ch * 8];
                *(uint4*)(dsm + dsts[piece] + r * 128 + ((ch ^ (r & 7)) << 4)) = v;
            }
    }

    float acc_o[4][4];
    float l[2] = {0.f, 0.f};
#pragma unroll
    for (int nt = 0; nt < 4; nt++)
#pragma unroll
        for (int q = 0; q < 4; q++) acc_o[nt][q] = 0.f;

    for (int j0 = 0; j0 < NJ; j0 += 64) {
        __syncthreads();
        {
            const __nv_bfloat16* srcs[4] = {g_kh, g_kl, g_vh, g_vl};
            const uint32_t dsts[4] = {Kh, Kl, Vh, Vl};
#pragma unroll
            for (int piece = 0; piece < 4; piece++)
#pragma unroll
                for (int p = 0; p < 2; p++) {
                    const int idx = p * 256 + tid;
                    const int r = idx >> 3, ch = idx & 7;
                    const uint4 v = *(const uint4*)&srcs[piece][(size_t)(j0 + r) * CS + h * DDIM + ch * 8];
                    *(uint4*)(dsm + dsts[piece] + r * 128 + ((ch ^ (r & 7)) << 4)) = v;
                }
        }
        __syncthreads();

        float acc_s[4][4];
#pragma unroll
        for (int nt = 0; nt < 4; nt++)
#pragma unroll
            for (int q = 0; q < 4; q++) acc_s[nt][q] = 0.f;

#pragma unroll
        for (int ks = 0; ks < 4; ks++) {
            uint32_t ah[4], al[4];
            {
                const int r = mt * 16 + a_row;
                const int ch = ks * 2 + a_kh;
                const uint32_t off = r * 128 + ((ch ^ (r & 7)) << 4);
                ldsm4(ah, sb + Qh + off);
                ldsm4(al, sb + Ql + off);
            }
            uint32_t bh[4][2], bl[4][2];
#pragma unroll
            for (int bq2 = 0; bq2 < 2; bq2++) {
                const int r = nh * 32 + bq2 * 16 + b_row;
                const int ch = ks * 2 + b_kh;
                const uint32_t off = r * 128 + ((ch ^ (r & 7)) << 4);
                uint32_t t[4];
                ldsm4(t, sb + Kh + off);
                bh[2 * bq2][0] = t[0]; bh[2 * bq2][1] = t[1];
                bh[2 * bq2 + 1][0] = t[2]; bh[2 * bq2 + 1][1] = t[3];
                ldsm4(t, sb + Kl + off);
                bl[2 * bq2][0] = t[0]; bl[2 * bq2][1] = t[1];
                bl[2 * bq2 + 1][0] = t[2]; bl[2 * bq2 + 1][1] = t[3];
            }
#pragma unroll
            for (int nt = 0; nt < 4; nt++) {
                mma16816(acc_s[nt], ah, bh[nt]);
                mma16816(acc_s[nt], ah, bl[nt]);
                mma16816(acc_s[nt], al, bh[nt]);
            }
        }

#pragma unroll
        for (int nt = 0; nt < 4; nt++)
#pragma unroll
            for (int half = 0; half < 2; half++) {
                const int rl = mt * 16 + g2 + half * 8;
                const int cl = nh * 32 + nt * 8 + tig * 2;
                const float2 zv = *(const float2*)
                    &g_z[((size_t)h * NI + (i0 + rl)) * NJ + j0 + cl];
                const float p0 = __expf(acc_s[nt][half * 2]     + zv.x);
                const float p1 = __expf(acc_s[nt][half * 2 + 1] + zv.y);
                l[half] += p0 + p1;
                __nv_bfloat16 h0, h1, l0, l1;
                cvt_hilo(p0, h0, l0); cvt_hilo(p1, h1, l1);
                const uint32_t byte = cl * 2;
                const uint32_t off = rl * 128 + ((((byte >> 4) ^ (rl & 7))) << 4) + (byte & 15);
                *(__nv_bfloat162*)(dsm + Ph + off) = __halves2bfloat162(h0, h1);
                *(__nv_bfloat162*)(dsm + Pl + off) = __halves2bfloat162(l0, l1);
            }
        __syncthreads();

#pragma unroll
        for (int ks = 0; ks < 4; ks++) {
            uint32_t ph_[4], pl_[4];
            {
                const int r = mt * 16 + a_row;
                const int ch = ks * 2 + a_kh;
                const uint32_t off = r * 128 + ((ch ^ (r & 7)) << 4);
                ldsm4(ph_, sb + Ph + off);
                ldsm4(pl_, sb + Pl + off);
            }
            uint32_t vh_[4][2], vl_[4][2];
#pragma unroll
            for (int bq2 = 0; bq2 < 2; bq2++) {
                const int r = ks * 16 + t_row;
                const int n0 = nh * 32 + bq2 * 16 + t_n8;
                const int ch = n0 >> 3;
                const uint32_t off = r * 128 + ((ch ^ (r & 7)) << 4);
                uint32_t t[4];
                ldsm4_t(t, sb + Vh + off);
                vh_[2 * bq2][0] = t[0]; vh_[2 * bq2][1] = t[1];
                vh_[2 * bq2 + 1][0] = t[2]; vh_[2 * bq2 + 1][1] = t[3];
                ldsm4_t(t, sb + Vl + off);
                vl_[2 * bq2][0] = t[0]; vl_[2 * bq2][1] = t[1];
                vl_[2 * bq2 + 1][0] = t[2]; vl_[2 * bq2 + 1][1] = t[3];
            }
#pragma unroll
            for (int nt = 0; nt < 4; nt++) {
                mma16816(acc_o[nt], ph_, vh_[nt]);
                mma16816(acc_o[nt], pl_, vh_[nt]);
                mma16816(acc_o[nt], ph_, vl_[nt]);
            }
        }
    }

#pragma unroll
    for (int half = 0; half < 2; half++) {
        l[half] += __shfl_xor_sync(0xffffffffu, l[half], 1);
        l[half] += __shfl_xor_sync(0xffffffffu, l[half], 2);
    }
    if (tig == 0) {
        ((float*)(dsm + LR))[(mt * 16 + g2) * 2 + nh]     = l[0];
        ((float*)(dsm + LR))[(mt * 16 + g2 + 8) * 2 + nh] = l[1];
    }
    __syncthreads();

#pragma unroll
    for (int half = 0; half < 2; half++) {
        const int rl = mt * 16 + g2 + half * 8;
        const float lt = ((float*)(dsm + LR))[rl * 2] + ((float*)(dsm + LR))[rl * 2 + 1];
        const float inv = 1.f / lt;
        const int row = i0 + rl;
#pragma unroll
        for (int nt = 0; nt < 4; nt++) {
            const int dcol = h * DDIM + nh * 32 + nt * 8 + tig * 2;
            const size_t pos = (size_t)row * CS + dcol;
            const float2 gv = *(const float2*)&g_g[pos];
            const float o0 = acc_o[nt][half * 2]     * inv * gv.x;
            const float o1 = acc_o[nt][half * 2 + 1] * inv * gv.y;
            __nv_bfloat16 h0, h1, l0, l1;
            cvt_hilo(o0, h0, l0); cvt_hilo(o1, h1, l1);
            *(__nv_bfloat162*)&g_go_h[pos] = __halves2bfloat162(h0, h1);
            *(__nv_bfloat162*)&g_go_l[pos] = __halves2bfloat162(l0, l1);
        }
    }
}

// =====================================================================
extern "C" void kernel_launch(void* const* d_in, const int* in_sizes, int n_in,
                              void* d_out, int out_size)
{
    (void)in_sizes; (void)n_in; (void)out_size;
    const float* s    = (const float*)d_in[0];
    const float* kin  = (const float*)d_in[1];
    const float* mask = (const float*)d_in[2];
    const float* bias = (const float*)d_in[3];
    const float* Wq   = (const float*)d_in[4];
    const float* bq   = (const float*)d_in[5];
    const float* Wk   = (const float*)d_in[6];
    const float* Wv   = (const float*)d_in[7];
    const float* Wg   = (const float*)d_in[8];
    const float* Wo   = (const float*)d_in[9];
    const float* Wz   = (const float*)d_in[10];
    float* out = (float*)d_out;

    // host-side attribute sets (idempotent, not stream ops)
    cudaFuncSetAttribute(proj_mma_kernel,
                         cudaFuncAttributeMaxDynamicSharedMemorySize, GEMM_SMEM);
    cudaFuncSetAttribute(final_mma_kernel,
                         cudaFuncAttributeMaxDynamicSharedMemorySize, GEMM_SMEM);
    cudaFuncSetAttribute(attn_kernel,
                         cudaFuncAttributeMaxDynamicSharedMemorySize, ATTN_SMEM);

    conv_kernel<<<7 * 64, 256>>>(s, kin, Wq, Wk, Wv, Wg, Wo);
    proj_mma_kernel<<<dim3(8, 8, 4), 256, GEMM_SMEM>>>(bq);
    z_kernel<<<2 * NI, 256>>>(bias, Wz, mask);
    attn_kernel<<<dim3(NI / 64, HD), 256, ATTN_SMEM>>>();
    final_mma_kernel<<<dim3(8, 8), 256, GEMM_SMEM>>>(out);
}

// round 15
// speedup vs baseline: 1.0993x; 1.0008x over previous
#include <cuda_runtime.h>
#include <cuda_bf16.h>
#include <cstdint>

#define CS   1024
#define HD   16
#define DDIM 64
#define CZ   128
#define NI   1024
#define NJ   1024

typedef unsigned long long ull;

// ---------------- scratch (device globals: allocation-free) ----------------
__device__ float g_g[NI * CS];                  // 4 MB (gate, fp32)
__device__ float g_z[(size_t)HD * NI * NJ];     // 64 MB

// bf16 hi/lo split matrices (2 MB each)
__device__ __nv_bfloat16 g_s_h[NI * CS],   g_s_l[NI * CS];
__device__ __nv_bfloat16 g_kin_h[NJ * CS], g_kin_l[NJ * CS];
__device__ __nv_bfloat16 g_wq_h[CS * CS],  g_wq_l[CS * CS];
__device__ __nv_bfloat16 g_wk_h[CS * CS],  g_wk_l[CS * CS];
__device__ __nv_bfloat16 g_wv_h[CS * CS],  g_wv_l[CS * CS];
__device__ __nv_bfloat16 g_wg_h[CS * CS],  g_wg_l[CS * CS];
__device__ __nv_bfloat16 g_wo_h[CS * CS],  g_wo_l[CS * CS];
__device__ __nv_bfloat16 g_qh[NI * CS],  g_ql[NI * CS];      // q/8 (bias folded)
__device__ __nv_bfloat16 g_kh[NJ * CS],  g_kl[NJ * CS];
__device__ __nv_bfloat16 g_vh[NJ * CS],  g_vl[NJ * CS];
__device__ __nv_bfloat16 g_go_h[NI * CS], g_go_l[NI * CS];   // g .* o from attn

// ---------------- packed fp32x2 helpers (z kernel) ----------------
static __device__ __forceinline__ ull f2pack(float x, float y) {
    ull r; asm("mov.b64 %0, {%1, %2};" : "=l"(r) : "f"(x), "f"(y)); return r;
}
static __device__ __forceinline__ ull f2dup(float x) {
    ull r; asm("mov.b64 %0, {%1, %1};" : "=l"(r) : "f"(x)); return r;
}
static __device__ __forceinline__ void ffma2(ull& d, ull a, ull b) {
    asm("fma.rn.f32x2 %0, %1, %2, %0;" : "+l"(d) : "l"(a), "l"(b));
}
static __device__ __forceinline__ float2 f2unpack(ull v) {
    float2 r; asm("mov.b64 {%0, %1}, %2;" : "=f"(r.x), "=f"(r.y) : "l"(v)); return r;
}

// ---------------- mma.sync / ldmatrix / cp.async helpers (baseline PTX) -----
static __device__ __forceinline__ uint32_t smem_to_u32(const void* p) {
    uint32_t a;
    asm("{ .reg .u64 t; cvta.to.shared.u64 t, %1; cvt.u32.u64 %0, t; }" : "=r"(a) : "l"(p));
    return a;
}
static __device__ __forceinline__ void ldsm4(uint32_t* r, uint32_t addr) {
    asm volatile("ldmatrix.sync.aligned.m8n8.x4.shared.b16 {%0,%1,%2,%3}, [%4];"
                 : "=r"(r[0]), "=r"(r[1]), "=r"(r[2]), "=r"(r[3]) : "r"(addr));
}
static __device__ __forceinline__ void ldsm4_t(uint32_t* r, uint32_t addr) {
    asm volatile("ldmatrix.sync.aligned.m8n8.x4.trans.shared.b16 {%0,%1,%2,%3}, [%4];"
                 : "=r"(r[0]), "=r"(r[1]), "=r"(r[2]), "=r"(r[3]) : "r"(addr));
}
static __device__ __forceinline__ void mma16816(float* c, const uint32_t* a, const uint32_t* b) {
    asm volatile("mma.sync.aligned.m16n8k16.row.col.f32.bf16.bf16.f32 "
                 "{%0,%1,%2,%3}, {%4,%5,%6,%7}, {%8,%9}, {%0,%1,%2,%3};"
                 : "+f"(c[0]), "+f"(c[1]), "+f"(c[2]), "+f"(c[3])
                 : "r"(a[0]), "r"(a[1]), "r"(a[2]), "r"(a[3]), "r"(b[0]), "r"(b[1]));
}
#define CP_ASYNC16(smem, gptr) \
    asm volatile("cp.async.cg.shared.global [%0], [%1], 16;" \
                 :: "r"(smem), "l"(gptr) : "memory")
#define CP_COMMIT() asm volatile("cp.async.commit_group;" ::: "memory")
#define CP_WAIT1()  asm volatile("cp.async.wait_group 1;" ::: "memory")
#define CP_WAIT0()  asm volatile("cp.async.wait_group 0;" ::: "memory")

static __device__ __forceinline__ void cvt_hilo(float v, __nv_bfloat16& h, __nv_bfloat16& l) {
    h = __float2bfloat16(v);
    l = __float2bfloat16(v - __bfloat162float(h));
}

// =====================================================================
// fp32 -> bf16 hi/lo conversion (s, kin, Wq, Wk, Wv, Wg, Wo)
// =====================================================================
__global__ __launch_bounds__(256) void conv_kernel(
    const float* __restrict__ s, const float* __restrict__ kin,
    const float* __restrict__ Wq, const float* __restrict__ Wk,
    const float* __restrict__ Wv, const float* __restrict__ Wg,
    const float* __restrict__ Wo)
{
    const int which = blockIdx.x >> 6;
    const int slice = blockIdx.x & 63;
    const float* src;
    __nv_bfloat16 *dh, *dl;
    switch (which) {
    case 0: src = s;   dh = g_s_h;   dl = g_s_l;   break;
    case 1: src = kin; dh = g_kin_h; dl = g_kin_l; break;
    case 2: src = Wq;  dh = g_wq_h;  dl = g_wq_l;  break;
    case 3: src = Wk;  dh = g_wk_h;  dl = g_wk_l;  break;
    case 4: src = Wv;  dh = g_wv_h;  dl = g_wv_l;  break;
    case 5: src = Wg;  dh = g_wg_h;  dl = g_wg_l;  break;
    default: src = Wo; dh = g_wo_h;  dl = g_wo_l;  break;
    }
    const int base = slice * 16384;
#pragma unroll 4
    for (int it = 0; it < 16; it++) {
        const int e = base + (it * 256 + threadIdx.x) * 4;
        const float4 v = *(const float4*)&src[e];
        __nv_bfloat16 h0, h1, h2, h3, l0, l1, l2, l3;
        cvt_hilo(v.x, h0, l0); cvt_hilo(v.y, h1, l1);
        cvt_hilo(v.z, h2, l2); cvt_hilo(v.w, h3, l3);
        *(__nv_bfloat162*)&dh[e]     = __halves2bfloat162(h0, h1);
        *(__nv_bfloat162*)&dh[e + 2] = __halves2bfloat162(h2, h3);
        *(__nv_bfloat162*)&dl[e]     = __halves2bfloat162(l0, l1);
        *(__nv_bfloat162*)&dl[e + 2] = __halves2bfloat162(l2, l3);
    }
}

// =====================================================================
// mma.sync bf16x3 GEMM, cp.async double-buffered BK=32 pipeline
// (R11/R13-measured). C[128x128 tile] = A @ B^T.
// 64B smem rows, swizzle ch ^ ((r>>1)&3).
// OUT: 0 fp32 plain, 1 (acc+bias)*0.125 -> bf16 hi/lo (q),
//      2 sigmoid -> fp32 (g), 3 plain -> bf16 hi/lo (k, v)
// smem: 2 stages x 4 pieces x 8KB = 64KB
// =====================================================================
#define GEMM_SMEM 65536

template <int OUT>
static __device__ void gemm_mma_body(
    const __nv_bfloat16* __restrict__ Ahg, const __nv_bfloat16* __restrict__ Alg,
    const __nv_bfloat16* __restrict__ Bhg, const __nv_bfloat16* __restrict__ Blg,
    const float* __restrict__ biasv, float* __restrict__ Cf,
    __nv_bfloat16* __restrict__ Ch, __nv_bfloat16* __restrict__ Cl, char* dsm)
{
    const int tid  = threadIdx.x;
    const int warp = tid >> 5, lane = tid & 31;
    const int m0w  = (warp & 3) * 32;
    const int n0w  = (warp >> 2) * 64;
    const int rowA0 = blockIdx.y * 128;
    const int rowB0 = blockIdx.x * 128;
    const uint32_t sbase = smem_to_u32(dsm);

    float acc[2][8][4];
#pragma unroll
    for (int mt = 0; mt < 2; mt++)
#pragma unroll
        for (int nt = 0; nt < 8; nt++)
#pragma unroll
            for (int q = 0; q < 4; q++) acc[mt][nt][q] = 0.f;

    const int a_row = lane & 15;
    const int a_kh  = lane >> 4;
    const int b_row = ((lane >> 4) & 1) * 8 + (lane & 7);
    const int b_kh  = (lane >> 3) & 1;

    const __nv_bfloat16* gsrc[4] = {Ahg, Alg, Bhg, Blg};
    const int grow[4] = {rowA0, rowA0, rowB0, rowB0};

    auto load_chunk = [&](int c, int stage) {
#pragma unroll
        for (int p = 0; p < 8; p++) {
            const int idx = p * 256 + tid;
            const int piece = p >> 1;              // compile-time per unrolled p
            const int rem = idx & 511;
            const int r = rem >> 2, ch = rem & 3;
            const uint32_t dst = sbase + stage * 32768 + piece * 8192
                               + r * 64 + ((ch ^ ((r >> 1) & 3)) << 4);
            CP_ASYNC16(dst, &gsrc[piece][(size_t)(grow[piece] + r) * CS + c * 32 + ch * 8]);
        }
        CP_COMMIT();
    };

    load_chunk(0, 0);
    for (int c = 0; c < 32; c++) {
        const int stage = c & 1;
        if (c + 1 < 32) { load_chunk(c + 1, stage ^ 1); CP_WAIT1(); }
        else            { CP_WAIT0(); }
        __syncthreads();
        const uint32_t sb0 = sbase + stage * 32768;
#pragma unroll
        for (int ks = 0; ks < 2; ks++) {
            uint32_t ah[2][4], al[2][4], bh[8][2], bl[8][2];
#pragma unroll
            for (int mt = 0; mt < 2; mt++) {
                const int r = m0w + mt * 16 + a_row;
                const int ch = ks * 2 + a_kh;
                const uint32_t off = r * 64 + ((ch ^ ((r >> 1) & 3)) << 4);
                ldsm4(ah[mt], sb0 + off);
                ldsm4(al[mt], sb0 + 8192 + off);
            }
#pragma unroll
            for (int bq2 = 0; bq2 < 4; bq2++) {
                const int r = n0w + bq2 * 16 + b_row;
                const int ch = ks * 2 + b_kh;
                const uint32_t off = r * 64 + ((ch ^ ((r >> 1) & 3)) << 4);
                uint32_t t[4];
                ldsm4(t, sb0 + 16384 + off);
                bh[2 * bq2][0] = t[0]; bh[2 * bq2][1] = t[1];
                bh[2 * bq2 + 1][0] = t[2]; bh[2 * bq2 + 1][1] = t[3];
                ldsm4(t, sb0 + 24576 + off);
                bl[2 * bq2][0] = t[0]; bl[2 * bq2][1] = t[1];
                bl[2 * bq2 + 1][0] = t[2]; bl[2 * bq2 + 1][1] = t[3];
            }
#pragma unroll
            for (int mt = 0; mt < 2; mt++)
#pragma unroll
                for (int nt = 0; nt < 8; nt++) {
                    mma16816(acc[mt][nt], ah[mt], bh[nt]);
                    mma16816(acc[mt][nt], ah[mt], bl[nt]);
                    mma16816(acc[mt][nt], al[mt], bh[nt]);
                }
        }
        __syncthreads();
    }

    const int g2 = lane >> 2, tig = lane & 3;
#pragma unroll
    for (int mt = 0; mt < 2; mt++)
#pragma unroll
        for (int nt = 0; nt < 8; nt++)
#pragma unroll
            for (int half = 0; half < 2; half++) {
                const int row = rowA0 + m0w + mt * 16 + g2 + half * 8;
                const int col = rowB0 + n0w + nt * 8 + tig * 2;
                float2 v = make_float2(acc[mt][nt][half * 2], acc[mt][nt][half * 2 + 1]);
                if (OUT == 1) {
                    v.x = (v.x + biasv[col]) * 0.125f;
                    v.y = (v.y + biasv[col + 1]) * 0.125f;
                } else if (OUT == 2) {
                    v.x = 1.f / (1.f + __expf(-v.x));
                    v.y = 1.f / (1.f + __expf(-v.y));
                }
                if (OUT == 0 || OUT == 2) {
                    *(float2*)&Cf[(size_t)row * CS + col] = v;
                } else {
                    __nv_bfloat16 h0, h1, l0, l1;
                    cvt_hilo(v.x, h0, l0); cvt_hilo(v.y, h1, l1);
                    *(__nv_bfloat162*)&Ch[(size_t)row * CS + col] = __halves2bfloat162(h0, h1);
                    *(__nv_bfloat162*)&Cl[(size_t)row * CS + col] = __halves2bfloat162(l0, l1);
                }
            }
}

__global__ __launch_bounds__(256) void proj_mma_kernel(const float* __restrict__ bq)
{
    extern __shared__ char dsm[];
    switch (blockIdx.z) {
    case 0: gemm_mma_body<1>(g_s_h,   g_s_l,   g_wq_h, g_wq_l, bq,      nullptr, g_qh, g_ql, dsm); break;
    case 1: gemm_mma_body<3>(g_kin_h, g_kin_l, g_wk_h, g_wk_l, nullptr, nullptr, g_kh, g_kl, dsm); break;
    case 2: gemm_mma_body<3>(g_kin_h, g_kin_l, g_wv_h, g_wv_l, nullptr, nullptr, g_vh, g_vl, dsm); break;
    default: gemm_mma_body<2>(g_s_h,  g_s_l,   g_wg_h, g_wg_l, nullptr, g_g,     nullptr, nullptr, dsm); break;
    }
}

__global__ __launch_bounds__(256) void final_mma_kernel(float* __restrict__ out)
{
    extern __shared__ char dsm[];
    gemm_mma_body<0>(g_go_h, g_go_l, g_wo_h, g_wo_l, nullptr, out, nullptr, nullptr, dsm);
}

// =====================================================================
// z_kernel: JT=2 with prefetch distance 2 (bv/nv/nnv, pipeline depth 3).
// Steady state: 4 LDG.128 per thread in flight -> 32 KB/SM outstanding.
// z[h,i,j] = bias[i,j,:]·Wz[:,h] + (1-mask[j])*(-1e6)
// =====================================================================
__global__ __launch_bounds__(256, 2) void z_kernel(
    const float* __restrict__ bias, const float* __restrict__ Wz,
    const float* __restrict__ mask)
{
    __shared__ ull Wzs[(HD / 2) * CZ];   // Wzs[hp*128+c] = (Wz[c][2hp], Wz[c][2hp+1])
    for (int t = threadIdx.x; t < (HD / 2) * CZ; t += 256) {
        const int hp = t >> 7, c = t & 127;
        Wzs[t] = f2pack(Wz[c * HD + hp * 2], Wz[c * HD + hp * 2 + 1]);
    }
    __syncthreads();

    const int idx = blockIdx.x;                     // 0..2047
    const int i   = idx >> 1;
    const int jb  = (idx & 1) * 512 + threadIdx.x;  // j = jb + t*256, t in {0,1}
    const float* base = bias + (size_t)i * NJ * CZ;

    ull acc2[2][HD / 2];
#pragma unroll
    for (int t = 0; t < 2; t++)
#pragma unroll
        for (int hp = 0; hp < HD / 2; hp++) acc2[t][hp] = 0ull;

    float4 bv[2], nv[2];
#pragma unroll
    for (int t = 0; t < 2; t++) {
        bv[t] = *(const float4*)&base[(size_t)(jb + t * 256) * CZ];
        nv[t] = *(const float4*)&base[(size_t)(jb + t * 256) * CZ + 4];
    }

    for (int c4 = 0; c4 < CZ; c4 += 4) {
        float4 nnv[2];
        if (c4 + 8 < CZ) {
#pragma unroll
            for (int t = 0; t < 2; t++)
                nnv[t] = *(const float4*)&base[(size_t)(jb + t * 256) * CZ + c4 + 8];
        }
        {
            ull d0[2], d1[2];
#pragma unroll
            for (int t = 0; t < 2; t++) { d0[t] = f2dup(bv[t].x); d1[t] = f2dup(bv[t].y); }
#pragma unroll
            for (int hp = 0; hp < HD / 2; hp++) {
                const ulonglong2 w = *(const ulonglong2*)&Wzs[hp * CZ + c4];
#pragma unroll
                for (int t = 0; t < 2; t++) {
                    ffma2(acc2[t][hp], d0[t], w.x);
                    ffma2(acc2[t][hp], d1[t], w.y);
                }
            }
        }
        {
            ull d0[2], d1[2];
#pragma unroll
            for (int t = 0; t < 2; t++) { d0[t] = f2dup(bv[t].z); d1[t] = f2dup(bv[t].w); }
#pragma unroll
            for (int hp = 0; hp < HD / 2; hp++) {
                const ulonglong2 w = *(const ulonglong2*)&Wzs[hp * CZ + c4 + 2];
#pragma unroll
                for (int t = 0; t < 2; t++) {
                    ffma2(acc2[t][hp], d0[t], w.x);
                    ffma2(acc2[t][hp], d1[t], w.y);
                }
            }
        }
#pragma unroll
        for (int t = 0; t < 2; t++) { bv[t] = nv[t]; nv[t] = nnv[t]; }
    }

#pragma unroll
    for (int t = 0; t < 2; t++) {
        const int j = jb + t * 256;
        const float mterm = (1.0f - mask[j]) * (-1000000.0f);
#pragma unroll
        for (int hp = 0; hp < HD / 2; hp++) {
            const float2 zz = f2unpack(acc2[t][hp]);
            g_z[((size_t)(2 * hp + 0) * NI + i) * NJ + j] = zz.x + mterm;
            g_z[((size_t)(2 * hp + 1) * NI + i) * NJ + j] = zz.y + mterm;
        }
    }
}

// =====================================================================
// Attention via mma.sync (R10-measured, unchanged)
// =====================================================================
#define ATTN_SMEM 66048

__global__ __launch_bounds__(256) void attn_kernel()
{
    extern __shared__ char dsm[];
    const uint32_t sb = smem_to_u32(dsm);
    const int tid  = threadIdx.x;
    const int warp = tid >> 5, lane = tid & 31;
    const int mt   = warp >> 1;
    const int nh   = warp & 1;
    const int g2   = lane >> 2, tig = lane & 3;
    const int h  = blockIdx.y;
    const int i0 = blockIdx.x * 64;

    const uint32_t Qh = 0, Ql = 8192, Kh = 16384, Kl = 24576,
                   Vh = 32768, Vl = 40960, Ph = 49152, Pl = 57344, LR = 65536;

    const int a_row = lane & 15;
    const int a_kh  = lane >> 4;
    const int b_row = ((lane >> 4) & 1) * 8 + (lane & 7);
    const int b_kh  = (lane >> 3) & 1;
    const int t_row = lane & 15;
    const int t_n8  = (lane >> 4) * 8;

    {
        const __nv_bfloat16* srcs[2] = {g_qh, g_ql};
        const uint32_t dsts[2] = {Qh, Ql};
#pragma unroll
        for (int piece = 0; piece < 2; piece++)
#pragma unroll
            for (int p = 0; p < 2; p++) {
                const int idx = p * 256 + tid;
                const int r = idx >> 3, ch = idx & 7;
                const uint4 v = *(const uint4*)&srcs[piece][(size_t)(i0 + r) * CS + h * DDIM + ch * 8];
                *(uint4*)(dsm + dsts[piece] + r * 128 + ((ch ^ (r & 7)) << 4)) = v;
            }
    }

    float acc_o[4][4];
    float l[2] = {0.f, 0.f};
#pragma unroll
    for (int nt = 0; nt < 4; nt++)
#pragma unroll
        for (int q = 0; q < 4; q++) acc_o[nt][q] = 0.f;

    for (int j0 = 0; j0 < NJ; j0 += 64) {
        __syncthreads();
        {
            const __nv_bfloat16* srcs[4] = {g_kh, g_kl, g_vh, g_vl};
            const uint32_t dsts[4] = {Kh, Kl, Vh, Vl};
#pragma unroll
            for (int piece = 0; piece < 4; piece++)
#pragma unroll
                for (int p = 0; p < 2; p++) {
                    const int idx = p * 256 + tid;
                    const int r = idx >> 3, ch = idx & 7;
                    const uint4 v = *(const uint4*)&srcs[piece][(size_t)(j0 + r) * CS + h * DDIM + ch * 8];
                    *(uint4*)(dsm + dsts[piece] + r * 128 + ((ch ^ (r & 7)) << 4)) = v;
                }
        }
        __syncthreads();

        float acc_s[4][4];
#pragma unroll
        for (int nt = 0; nt < 4; nt++)
#pragma unroll
            for (int q = 0; q < 4; q++) acc_s[nt][q] = 0.f;

#pragma unroll
        for (int ks = 0; ks < 4; ks++) {
            uint32_t ah[4], al[4];
            {
                const int r = mt * 16 + a_row;
                const int ch = ks * 2 + a_kh;
                const uint32_t off = r * 128 + ((ch ^ (r & 7)) << 4);
                ldsm4(ah, sb + Qh + off);
                ldsm4(al, sb + Ql + off);
            }
            uint32_t bh[4][2], bl[4][2];
#pragma unroll
            for (int bq2 = 0; bq2 < 2; bq2++) {
                const int r = nh * 32 + bq2 * 16 + b_row;
                const int ch = ks * 2 + b_kh;
                const uint32_t off = r * 128 + ((ch ^ (r & 7)) << 4);
                uint32_t t[4];
                ldsm4(t, sb + Kh + off);
                bh[2 * bq2][0] = t[0]; bh[2 * bq2][1] = t[1];
                bh[2 * bq2 + 1][0] = t[2]; bh[2 * bq2 + 1][1] = t[3];
                ldsm4(t, sb + Kl + off);
                bl[2 * bq2][0] = t[0]; bl[2 * bq2][1] = t[1];
                bl[2 * bq2 + 1][0] = t[2]; bl[2 * bq2 + 1][1] = t[3];
            }
#pragma unroll
            for (int nt = 0; nt < 4; nt++) {
                mma16816(acc_s[nt], ah, bh[nt]);
                mma16816(acc_s[nt], ah, bl[nt]);
                mma16816(acc_s[nt], al, bh[nt]);
            }
        }

#pragma unroll
        for (int nt = 0; nt < 4; nt++)
#pragma unroll
            for (int half = 0; half < 2; half++) {
                const int rl = mt * 16 + g2 + half * 8;
                const int cl = nh * 32 + nt * 8 + tig * 2;
                const float2 zv = *(const float2*)
                    &g_z[((size_t)h * NI + (i0 + rl)) * NJ + j0 + cl];
                const float p0 = __expf(acc_s[nt][half * 2]     + zv.x);
                const float p1 = __expf(acc_s[nt][half * 2 + 1] + zv.y);
                l[half] += p0 + p1;
                __nv_bfloat16 h0, h1, l0, l1;
                cvt_hilo(p0, h0, l0); cvt_hilo(p1, h1, l1);
                const uint32_t byte = cl * 2;
                const uint32_t off = rl * 128 + ((((byte >> 4) ^ (rl & 7))) << 4) + (byte & 15);
                *(__nv_bfloat162*)(dsm + Ph + off) = __halves2bfloat162(h0, h1);
                *(__nv_bfloat162*)(dsm + Pl + off) = __halves2bfloat162(l0, l1);
            }
        __syncthreads();

#pragma unroll
        for (int ks = 0; ks < 4; ks++) {
            uint32_t ph_[4], pl_[4];
            {
                const int r = mt * 16 + a_row;
                const int ch = ks * 2 + a_kh;
                const uint32_t off = r * 128 + ((ch ^ (r & 7)) << 4);
                ldsm4(ph_, sb + Ph + off);
                ldsm4(pl_, sb + Pl + off);
            }
            uint32_t vh_[4][2], vl_[4][2];
#pragma unroll
            for (int bq2 = 0; bq2 < 2; bq2++) {
                const int r = ks * 16 + t_row;
                const int n0 = nh * 32 + bq2 * 16 + t_n8;
                const int ch = n0 >> 3;
                const uint32_t off = r * 128 + ((ch ^ (r & 7)) << 4);
                uint32_t t[4];
                ldsm4_t(t, sb + Vh + off);
                vh_[2 * bq2][0] = t[0]; vh_[2 * bq2][1] = t[1];
                vh_[2 * bq2 + 1][0] = t[2]; vh_[2 * bq2 + 1][1] = t[3];
                ldsm4_t(t, sb + Vl + off);
                vl_[2 * bq2][0] = t[0]; vl_[2 * bq2][1] = t[1];
                vl_[2 * bq2 + 1][0] = t[2]; vl_[2 * bq2 + 1][1] = t[3];
            }
#pragma unroll
            for (int nt = 0; nt < 4; nt++) {
                mma16816(acc_o[nt], ph_, vh_[nt]);
                mma16816(acc_o[nt], pl_, vh_[nt]);
                mma16816(acc_o[nt], ph_, vl_[nt]);
            }
        }
    }

#pragma unroll
    for (int half = 0; half < 2; half++) {
        l[half] += __shfl_xor_sync(0xffffffffu, l[half], 1);
        l[half] += __shfl_xor_sync(0xffffffffu, l[half], 2);
    }
    if (tig == 0) {
        ((float*)(dsm + LR))[(mt * 16 + g2) * 2 + nh]     = l[0];
        ((float*)(dsm + LR))[(mt * 16 + g2 + 8) * 2 + nh] = l[1];
    }
    __syncthreads();

#pragma unroll
    for (int half = 0; half < 2; half++) {
        const int rl = mt * 16 + g2 + half * 8;
        const float lt = ((float*)(dsm + LR))[rl * 2] + ((float*)(dsm + LR))[rl * 2 + 1];
        const float inv = 1.f / lt;
        const int row = i0 + rl;
#pragma unroll
        for (int nt = 0; nt < 4; nt++) {
            const int dcol = h * DDIM + nh * 32 + nt * 8 + tig * 2;
            const size_t pos = (size_t)row * CS + dcol;
            const float2 gv = *(const float2*)&g_g[pos];
            const float o0 = acc_o[nt][half * 2]     * inv * gv.x;
            const float o1 = acc_o[nt][half * 2 + 1] * inv * gv.y;
            __nv_bfloat16 h0, h1, l0, l1;
            cvt_hilo(o0, h0, l0); cvt_hilo(o1, h1, l1);
            *(__nv_bfloat162*)&g_go_h[pos] = __halves2bfloat162(h0, h1);
            *(__nv_bfloat162*)&g_go_l[pos] = __halves2bfloat162(l0, l1);
        }
    }
}

// =====================================================================
extern "C" void kernel_launch(void* const* d_in, const int* in_sizes, int n_in,
                              void* d_out, int out_size)
{
    (void)in_sizes; (void)n_in; (void)out_size;
    const float* s    = (const float*)d_in[0];
    const float* kin  = (const float*)d_in[1];
    const float* mask = (const float*)d_in[2];
    const float* bias = (const float*)d_in[3];
    const float* Wq   = (const float*)d_in[4];
    const float* bq   = (const float*)d_in[5];
    const float* Wk   = (const float*)d_in[6];
    const float* Wv   = (const float*)d_in[7];
    const float* Wg   = (const float*)d_in[8];
    const float* Wo   = (const float*)d_in[9];
    const float* Wz   = (const float*)d_in[10];
    float* out = (float*)d_out;

    // host-side attribute sets (idempotent, not stream ops)
    cudaFuncSetAttribute(proj_mma_kernel,
                         cudaFuncAttributeMaxDynamicSharedMemorySize, GEMM_SMEM);
    cudaFuncSetAttribute(final_mma_kernel,
                         cudaFuncAttributeMaxDynamicSharedMemorySize, GEMM_SMEM);
    cudaFuncSetAttribute(attn_kernel,
                         cudaFuncAttributeMaxDynamicSharedMemorySize, ATTN_SMEM);

    conv_kernel<<<7 * 64, 256>>>(s, kin, Wq, Wk, Wv, Wg, Wo);
    proj_mma_kernel<<<dim3(8, 8, 4), 256, GEMM_SMEM>>>(bq);
    z_kernel<<<2 * NI, 256>>>(bias, Wz, mask);
    attn_kernel<<<dim3(NI / 64, HD), 256, ATTN_SMEM>>>();
    final_mma_kernel<<<dim3(8, 8), 256, GEMM_SMEM>>>(out);
}